// round 16
// baseline (speedup 1.0000x reference)
#include <cuda_runtime.h>
#include <cuda_bf16.h>
#include <cstdint>

// Problem shapes (fixed by setup_inputs): B=4, N=128, C_IN=C_OUT=32, X=3.
#define BZ 4
#define NN 128

// ---------------------------------------------------------------------------
// Scratch (no allocations allowed -> __device__ globals)
// ---------------------------------------------------------------------------
// Per-(z,c) BASE sums: row = 128 floats [b][k]: b=0: p0 = sum_d f;
// b=1..3: p1[x] = sum_d g[d,x]*f.
__device__ float4 g_base[BZ][NN][32];     // 256 KB
__device__ float  g_W12g[9 * 32 * 32];    // W12[yx][i][k] = sum_j W2[y,i,j]*W1[x,j,k]
__device__ float  g_U[BZ][512];           // U0[32] | U1[96] | U2[96] | U3[288]

// Robust scalar load: handles int32 or float32 encodings of n_norm.
__device__ __forceinline__ float load_scalar_f(const void* p) {
    int iv = *(const int*)p;
    int ex = (iv >> 23) & 0xFF;
    if (ex > 60 && ex < 200) return __int_as_float(iv);
    return (float)iv;
}

// ---------------------------------------------------------------------------
// K1: grid = BZ*NN + 9, 256 threads — EXACT r11 shape (measured optimum,
// 5.73-5.89us across three runs; 512-thr, 2-row, and manual-reorder variants
// all measured slower).
//   blocks [0..511]: per-(z,c) base sums.
//   blocks [512..520]: W12[yx] = W2[y] @ W1[x] via smem staging (reg-light).
// ---------------------------------------------------------------------------
__global__ void __launch_bounds__(256, 6) k_partial(const float* __restrict__ feat,
                                                    const float* __restrict__ geo,
                                                    const float* __restrict__ W1,
                                                    const float* __restrict__ W2) {
    int zc = blockIdx.x;
    int t = threadIdx.x;        // 256

    // ---- W12 rider blocks: stage weights in smem, then LDS-fed FMA chains ----
    if (zc >= BZ * NN) {
        __shared__ float sw1[1024];   // W1[x][j][k]
        __shared__ float sw2[1024];   // W2[y][i][j]
        int yx = zc - BZ * NN;        // 0..8
        int y = yx / 3, x = yx - y * 3;
        #pragma unroll
        for (int r = 0; r < 4; r++) {
            sw2[t + r * 256] = W2[y * 1024 + t + r * 256];
            sw1[t + r * 256] = W1[x * 1024 + t + r * 256];
        }
        __syncthreads();
        #pragma unroll
        for (int r = 0; r < 4; r++) {
            int idx = t + r * 256;    // i*32 + k
            int i = idx >> 5, k = idx & 31;
            float acc = 0.f;
            #pragma unroll
            for (int j = 0; j < 32; j++) acc = fmaf(sw2[i * 32 + j], sw1[j * 32 + k], acc);
            g_W12g[yx * 1024 + idx] = acc;
        }
        return;
    }

    int z = zc >> 7;
    int kq   = t & 7;           // which float4 within the 32-float k-row
    int dgrp = t >> 3;          // 0..31

    __shared__ float  sgeo[3][NN];     // geo[z] transposed: [comp][d]
    __shared__ float4 smq[4][32][8];   // [comp][dgrp][kq], 16 KB
    __shared__ float  red[4][32];      // reduced sums [comp][k]

    if (t < NN * 3) {
        int d = t / 3, comp = t - d * 3;
        sgeo[comp][d] = geo[z * NN * 3 + t];
    }
    if (t + 256 < NN * 3) {
        int idx = t + 256;
        int d = idx / 3, comp = idx - d * 3;
        sgeo[comp][d] = geo[z * NN * 3 + idx];
    }
    __syncthreads();

    const float4* f4 = (const float4*)(feat + ((size_t)zc << 12));
    float4 s0 = make_float4(0.f, 0.f, 0.f, 0.f);
    float4 sx = s0, sy = s0, sz2 = s0;

    #pragma unroll
    for (int it = 0; it < 4; it++) {
        int d = dgrp + it * 32;
        float4 f = f4[d * 8 + kq];
        float g0 = sgeo[0][d], g1 = sgeo[1][d], g2 = sgeo[2][d];
        s0.x += f.x;  s0.y += f.y;  s0.z += f.z;  s0.w += f.w;
        sx.x = fmaf(f.x, g0, sx.x);  sx.y = fmaf(f.y, g0, sx.y);
        sx.z = fmaf(f.z, g0, sx.z);  sx.w = fmaf(f.w, g0, sx.w);
        sy.x = fmaf(f.x, g1, sy.x);  sy.y = fmaf(f.y, g1, sy.y);
        sy.z = fmaf(f.z, g1, sy.z);  sy.w = fmaf(f.w, g1, sy.w);
        sz2.x = fmaf(f.x, g2, sz2.x);  sz2.y = fmaf(f.y, g2, sz2.y);
        sz2.z = fmaf(f.z, g2, sz2.z);  sz2.w = fmaf(f.w, g2, sz2.w);
    }

    smq[0][dgrp][kq] = s0;
    smq[1][dgrp][kq] = sx;
    smq[2][dgrp][kq] = sy;
    smq[3][dgrp][kq] = sz2;
    __syncthreads();

    // Reduce over 32 dgrps: threads t<128 -> (comp = t>>5, k = t&31).
    if (t < 128) {
        int comp = t >> 5;
        int k = t & 31;
        const float* p = (const float*)&smq[comp][0][0];  // 1024 floats
        float s = 0.f;
        #pragma unroll
        for (int dg = 0; dg < 32; dg++) s += p[dg * 32 + k];
        red[comp][k] = s;
    }
    __syncthreads();

    // Write the 128-float base row as 32 float4s (coalesced 512B).
    if (t < 32) {
        int c = zc & (NN - 1);
        g_base[z][c][t] = ((const float4*)red)[t];
    }
}

// ---------------------------------------------------------------------------
// K2: per-z middle (r11 body + PDL). grid = B, 512 threads.
// ---------------------------------------------------------------------------
__global__ void __launch_bounds__(512, 1) k_middle(const float* __restrict__ geo) {
    int z = blockIdx.x;
    int t = threadIdx.x;  // 512

    __shared__ float sW12[9 * 32 * 32];  // 36 KB: [yx][i][k]
    __shared__ float sM[16][32];         // 2 KB
    __shared__ float sgeo[3][NN];        // 1.5 KB

    // Independent prologue: geo staging (input only).
    if (t < NN * 3) {
        int c = t / 3, comp = t - c * 3;
        sgeo[comp][c] = geo[z * NN * 3 + t];
    }

    // Wait for k_partial grid (g_base + g_W12g) to complete.
    cudaGridDependencySynchronize();

    // (0) copy W12: 2304 float4 across 512 threads (coalesced, independent).
    {
        float4* s4 = (float4*)sW12;
        const float4* g4 = (const float4*)g_W12g;
        #pragma unroll
        for (int r = 0; r < 4; r++) s4[t + r * 512] = g4[t + r * 512];
        if (t < 2304 - 2048) s4[t + 2048] = g4[t + 2048];
    }

    // (1) gy-weighted reduce over c. One (m,k) slot per thread. Needs sgeo.
    __syncthreads();
    {
        int m = t >> 5;
        int k = t & 31;
        int b, y;
        if (m < 4)      { b = m;  y = -1; }
        else if (m < 7) { b = 0;  y = m - 4; }
        else            { int mm = m - 7; y = mm / 3; b = 1 + (mm - y * 3); }

        const float* base = (const float*)&g_base[z][0][0] + b * 32 + k;  // stride 128
        float s = 0.f;
        if (y < 0) {
            #pragma unroll 16
            for (int c = 0; c < NN; c++) s += base[c * 128];
        } else {
            const float* gy = &sgeo[y][0];
            #pragma unroll 16
            for (int c = 0; c < NN; c++) s = fmaf(base[c * 128], gy[c], s);
        }
        (&sM[0][0])[t] = s;
    }
    __syncthreads();

    // (2) U from shared. One output per thread.
    float r = 0.f;
    if (t < 32) {
        int i = t;
        for (int yx = 0; yx < 9; yx++) {
            const float* w = &sW12[(yx * 32 + i) * 32];
            const float* m = &sM[7 + yx][0];
            #pragma unroll
            for (int k = 0; k < 32; k++) r = fmaf(w[k], m[k], r);
        }
    } else if (t < 128) {
        int x = (t - 32) >> 5, i = t & 31;
        for (int y = 0; y < 3; y++) {
            const float* w = &sW12[((y * 3 + x) * 32 + i) * 32];
            const float* m = &sM[4 + y][0];
            #pragma unroll
            for (int k = 0; k < 32; k++) r = fmaf(w[k], m[k], r);
        }
    } else if (t < 224) {
        int y = (t - 128) >> 5, i = t & 31;
        for (int x = 0; x < 3; x++) {
            const float* w = &sW12[((y * 3 + x) * 32 + i) * 32];
            const float* m = &sM[1 + x][0];
            #pragma unroll
            for (int k = 0; k < 32; k++) r = fmaf(w[k], m[k], r);
        }
    } else {
        int m3 = t - 224;
        int yx = m3 >> 5, i = m3 & 31;
        const float* w = &sW12[(yx * 32 + i) * 32];
        const float* m = &sM[0][0];
        #pragma unroll
        for (int k = 0; k < 32; k++) r = fmaf(w[k], m[k], r);
    }
    g_U[z][t] = r;
}

// ---------------------------------------------------------------------------
// K3: output expansion (r15 2-row version — measured better than 1-row).
// grid = BZ*NN/2 = 256, 256 threads. TWO a-rows per block: sU + geo staged
// once; V computed by ALL 256 threads; 8 float4 stores per thread.
// ---------------------------------------------------------------------------
__global__ void __launch_bounds__(256) k_expand(const float* __restrict__ geo,
                                                float* __restrict__ out,
                                                const void* __restrict__ n_norm_ptr) {
    int blk = blockIdx.x;
    int z  = blk >> 6;
    int a0 = (blk & 63) * 2;
    int t = threadIdx.x;  // 256

    __shared__ float sU[512];
    __shared__ float sg[NN * 3];
    __shared__ float sV[2][128];   // [row][slot]: V0[0:32] | V1[x*32+i + 32]

    // Independent prologue: geo staging (input only).
    for (int idx = t; idx < NN * 3; idx += 256) sg[idx] = geo[z * NN * 3 + idx];

    // Wait for k_middle grid (g_U) to complete.
    cudaGridDependencySynchronize();

    sU[t] = g_U[z][t];
    sU[t + 256] = g_U[z][t + 256];
    __syncthreads();

    float inv_n = 1.0f / load_scalar_f(n_norm_ptr);

    // V for both rows: 256 slots = 2 rows x 128.
    {
        int row  = t >> 7;          // 0 or 1
        int slot = t & 127;
        int a = a0 + row;
        float ga0 = sg[a * 3 + 0], ga1 = sg[a * 3 + 1], ga2 = sg[a * 3 + 2];
        float v;
        if (slot < 32) {
            int i = slot;
            v = sU[i] - (ga0 * sU[128 + i] + ga1 * sU[160 + i] + ga2 * sU[192 + i]);
        } else {
            int x = (slot - 32) >> 5, i = slot & 31;
            v = -sU[32 + x * 32 + i]
              + ga0 * sU[224 + (0 * 3 + x) * 32 + i]
              + ga1 * sU[224 + (1 * 3 + x) * 32 + i]
              + ga2 * sU[224 + (2 * 3 + x) * 32 + i];
        }
        sV[row][slot] = inv_n * v;
    }
    __syncthreads();

    int i4   = t & 7;    // which float4 of the 32-float output row
    int bgrp = t >> 3;   // 0..31

    const float4* sV0 = (const float4*)&sV[0][0];
    const float4* sV1 = (const float4*)&sV[1][0];
    float4 p0  = sV0[i4],      q0  = sV1[i4];
    float4 p10 = sV0[8 + i4],  q10 = sV1[8 + i4];
    float4 p11 = sV0[16 + i4], q11 = sV1[16 + i4];
    float4 p12 = sV0[24 + i4], q12 = sV1[24 + i4];

    float4* oA = (float4*)(out + ((size_t)(z * NN + a0) << 12));
    float4* oB = oA + 1024;
    #pragma unroll
    for (int it = 0; it < 4; it++) {
        int b = bgrp + it * 32;
        float gb0 = sg[b * 3 + 0], gb1 = sg[b * 3 + 1], gb2 = sg[b * 3 + 2];
        float4 va, vb;
        va.x = fmaf(gb2, p12.x, fmaf(gb1, p11.x, fmaf(gb0, p10.x, p0.x)));
        va.y = fmaf(gb2, p12.y, fmaf(gb1, p11.y, fmaf(gb0, p10.y, p0.y)));
        va.z = fmaf(gb2, p12.z, fmaf(gb1, p11.z, fmaf(gb0, p10.z, p0.z)));
        va.w = fmaf(gb2, p12.w, fmaf(gb1, p11.w, fmaf(gb0, p10.w, p0.w)));
        vb.x = fmaf(gb2, q12.x, fmaf(gb1, q11.x, fmaf(gb0, q10.x, q0.x)));
        vb.y = fmaf(gb2, q12.y, fmaf(gb1, q11.y, fmaf(gb0, q10.y, q0.y)));
        vb.z = fmaf(gb2, q12.z, fmaf(gb1, q11.z, fmaf(gb0, q10.z, q0.z)));
        vb.w = fmaf(gb2, q12.w, fmaf(gb1, q11.w, fmaf(gb0, q10.w, q0.w)));
        oA[b * 8 + i4] = va;
        oB[b * 8 + i4] = vb;
    }
}

// ---------------------------------------------------------------------------
// kernel_launch — k_middle and k_expand launched with PDL
// (programmatic stream serialization) to hide launch gaps.
// ---------------------------------------------------------------------------
extern "C" void kernel_launch(void* const* d_in, const int* in_sizes, int n_in,
                              void* d_out, int out_size) {
    const float* feat = (const float*)d_in[0];
    const float* geo  = (const float*)d_in[1];
    const float* W1   = (const float*)d_in[2];
    const float* W2   = (const float*)d_in[3];
    const void*  nrm  = (n_in > 4) ? d_in[4] : nullptr;
    float* out = (float*)d_out;

    k_partial<<<BZ * NN + 9, 256>>>(feat, geo, W1, W2);

    cudaLaunchAttribute attr[1];
    attr[0].id = cudaLaunchAttributeProgrammaticStreamSerialization;
    attr[0].val.programmaticStreamSerializationAllowed = 1;

    {
        cudaLaunchConfig_t cfg = {};
        cfg.gridDim = dim3(BZ);
        cfg.blockDim = dim3(512);
        cfg.attrs = attr;
        cfg.numAttrs = 1;
        cudaLaunchKernelEx(&cfg, k_middle, geo);
    }
    {
        cudaLaunchConfig_t cfg = {};
        cfg.gridDim = dim3(BZ * NN / 2);
        cfg.blockDim = dim3(256);
        cfg.attrs = attr;
        cfg.numAttrs = 1;
        cudaLaunchKernelEx(&cfg, k_expand, geo, out, (const void*)nrm);
    }
}